// round 7
// baseline (speedup 1.0000x reference)
#include <cuda_runtime.h>
#include <cuda_bf16.h>
#include <math.h>
#include <stdint.h>

#define BB 64
#define TT 20
#define CC 512
#define HWD 196
#define VV 10000
#define EE 256
#define UU 512
#define G4 2048            // 4*U
#define XD 1280            // E + C + U
#define IHK 768            // C + E
#define LOGITS_SZ (BB*TT*VV)
#define ATTN_SZ (BB*TT*HWD)
#define KSPLIT 4

#define KT 32              // K-tile (bf16 elems)
#define APADH 40           // padded smem row stride in bf16 halves (80B): MMA LDS conflict-free

// ---------------- device scratch ----------------
__device__ __nv_bfloat16 g_ftT_h[(size_t)BB*HWD*CC];   // featsT split [B*HW, C]
__device__ __nv_bfloat16 g_ftT_l[(size_t)BB*HWD*CC];
__device__ __nv_bfloat16 g_Wkey_h[(size_t)UU*CC];
__device__ __nv_bfloat16 g_Wkey_l[(size_t)UU*CC];
__device__ __nv_bfloat16 g_Wcat_h[(size_t)G4*XD];
__device__ __nv_bfloat16 g_Wcat_l[(size_t)G4*XD];
__device__ __nv_bfloat16 g_Wout_h[(size_t)VV*XD];
__device__ __nv_bfloat16 g_Wout_l[(size_t)VV*XD];
__device__ __nv_bfloat16 g_x_h[BB*XD];                 // [emb | a | hid]
__device__ __nv_bfloat16 g_x_l[BB*XD];
__device__ __nv_bfloat16 g_outs_h[(size_t)BB*TT*XD];   // [hid | a | emb]
__device__ __nv_bfloat16 g_outs_l[(size_t)BB*TT*XD];
__device__ float g_fm[BB*CC];
__device__ float g_keys[(size_t)BB*HWD*UU];            // [B*HW, U] fp32
__device__ float g_hid[BB*UU];
__device__ float g_cell[BB*UU];
__device__ float g_capemb[(size_t)BB*TT*EE];
__device__ float g_gpart[(size_t)KSPLIT*BB*G4];
__device__ float g_bcat[G4];

// ---------------- helpers ----------------
__device__ __forceinline__ void split2(float v, __nv_bfloat16* ph, __nv_bfloat16* pl) {
    __nv_bfloat16 h = __float2bfloat16(v);
    *ph = h;
    *pl = __float2bfloat16(v - __bfloat162float(h));
}
__device__ __forceinline__ void mma16816(float* c, const uint32_t* a, const uint32_t* b) {
    asm volatile(
        "mma.sync.aligned.m16n8k16.row.col.f32.bf16.bf16.f32 "
        "{%0,%1,%2,%3}, {%4,%5,%6,%7}, {%8,%9}, {%0,%1,%2,%3};"
        : "+f"(c[0]), "+f"(c[1]), "+f"(c[2]), "+f"(c[3])
        : "r"(a[0]), "r"(a[1]), "r"(a[2]), "r"(a[3]), "r"(b[0]), "r"(b[1]));
}

// ============================================================================
// HMMA bf16-split NT GEMM on pre-split operands:
//   C[m,n] = sum_k A[m,k]*B[n,k] (+ bias[n]),  A ~ Ah+Al, B ~ Bh+Bl
// Tile 128x128, K-tile 32. grid = (ceil(N/128), ceil(M/128), nsplit).
// nsplit>1: partials at C + z*M*ldc, bias must be nullptr. (K/nsplit)%32==0.
// ============================================================================
__global__ void __launch_bounds__(256) hgemm(
    const __nv_bfloat16* __restrict__ Ah, const __nv_bfloat16* __restrict__ Al, int lda,
    const __nv_bfloat16* __restrict__ Bh, const __nv_bfloat16* __restrict__ Bl, int ldb,
    const float* __restrict__ bias,
    float* __restrict__ Cm, int ldc,
    int M, int N, int K)
{
    __shared__ __nv_bfloat16 sAh[128 * APADH];
    __shared__ __nv_bfloat16 sAl[128 * APADH];
    __shared__ __nv_bfloat16 sBh[128 * APADH];
    __shared__ __nv_bfloat16 sBl[128 * APADH];

    int tid = threadIdx.x, lane = tid & 31, wid = tid >> 5;
    int m0 = blockIdx.y * 128, n0 = blockIdx.x * 128;
    int kPer = K / gridDim.z;
    int kBeg = blockIdx.z * kPer;
    Cm += (size_t)blockIdx.z * (size_t)M * ldc;

    int warp_m = wid & 1;       // 2 warps over M (64 rows)
    int warp_n = wid >> 1;      // 4 warps over N (32 cols)

    float acc[4][4][4];
    #pragma unroll
    for (int i = 0; i < 4; i++)
        #pragma unroll
        for (int j = 0; j < 4; j++)
            #pragma unroll
            for (int q = 0; q < 4; q++) acc[i][j][q] = 0.f;

    // loader: thread -> (row 0..127, 32B half-row); per array 2x uint4
    int lrow = tid >> 1;
    int lu   = (tid & 1) * 16;          // halves offset within 32-elem row
    bool aok = (m0 + lrow) < M;
    bool bok = (n0 + lrow) < N;
    const __nv_bfloat16* ApH = Ah + (size_t)(m0 + lrow) * lda + kBeg + lu;
    const __nv_bfloat16* ApL = Al + (size_t)(m0 + lrow) * lda + kBeg + lu;
    const __nv_bfloat16* BpH = Bh + (size_t)(n0 + lrow) * ldb + kBeg + lu;
    const __nv_bfloat16* BpL = Bl + (size_t)(n0 + lrow) * ldb + kBeg + lu;
    int sbase = lrow * APADH + lu;
    uint4 z4 = make_uint4(0, 0, 0, 0);

    for (int k0 = 0; k0 < kPer; k0 += KT) {
        __syncthreads();
        uint4 v0, v1;
        v0 = aok ? *(const uint4*)(ApH + k0) : z4;
        v1 = aok ? *(const uint4*)(ApH + k0 + 8) : z4;
        *(uint4*)&sAh[sbase] = v0; *(uint4*)&sAh[sbase + 8] = v1;
        v0 = aok ? *(const uint4*)(ApL + k0) : z4;
        v1 = aok ? *(const uint4*)(ApL + k0 + 8) : z4;
        *(uint4*)&sAl[sbase] = v0; *(uint4*)&sAl[sbase + 8] = v1;
        v0 = bok ? *(const uint4*)(BpH + k0) : z4;
        v1 = bok ? *(const uint4*)(BpH + k0 + 8) : z4;
        *(uint4*)&sBh[sbase] = v0; *(uint4*)&sBh[sbase + 8] = v1;
        v0 = bok ? *(const uint4*)(BpL + k0) : z4;
        v1 = bok ? *(const uint4*)(BpL + k0 + 8) : z4;
        *(uint4*)&sBl[sbase] = v0; *(uint4*)&sBl[sbase + 8] = v1;
        __syncthreads();

        #pragma unroll
        for (int ks = 0; ks < 2; ks++) {
            int kb = ks * 16 + (lane & 3) * 2;
            uint32_t ah[4][4], al[4][4], bh[4][2], bl[4][2];
            #pragma unroll
            for (int mi = 0; mi < 4; mi++) {
                int r = warp_m * 64 + mi * 16 + (lane >> 2);
                ah[mi][0] = *(const uint32_t*)&sAh[r * APADH + kb];
                ah[mi][1] = *(const uint32_t*)&sAh[(r + 8) * APADH + kb];
                ah[mi][2] = *(const uint32_t*)&sAh[r * APADH + kb + 8];
                ah[mi][3] = *(const uint32_t*)&sAh[(r + 8) * APADH + kb + 8];
                al[mi][0] = *(const uint32_t*)&sAl[r * APADH + kb];
                al[mi][1] = *(const uint32_t*)&sAl[(r + 8) * APADH + kb];
                al[mi][2] = *(const uint32_t*)&sAl[r * APADH + kb + 8];
                al[mi][3] = *(const uint32_t*)&sAl[(r + 8) * APADH + kb + 8];
            }
            #pragma unroll
            for (int ni = 0; ni < 4; ni++) {
                int r = warp_n * 32 + ni * 8 + (lane >> 2);
                bh[ni][0] = *(const uint32_t*)&sBh[r * APADH + kb];
                bh[ni][1] = *(const uint32_t*)&sBh[r * APADH + kb + 8];
                bl[ni][0] = *(const uint32_t*)&sBl[r * APADH + kb];
                bl[ni][1] = *(const uint32_t*)&sBl[r * APADH + kb + 8];
            }
            #pragma unroll
            for (int mi = 0; mi < 4; mi++)
                #pragma unroll
                for (int ni = 0; ni < 4; ni++) {
                    mma16816(acc[mi][ni], ah[mi], bh[ni]);
                    mma16816(acc[mi][ni], ah[mi], bl[ni]);
                    mma16816(acc[mi][ni], al[mi], bh[ni]);
                }
        }
    }

    #pragma unroll
    for (int mi = 0; mi < 4; mi++) {
        int m = m0 + warp_m * 64 + mi * 16 + (lane >> 2);
        #pragma unroll
        for (int ni = 0; ni < 4; ni++) {
            int n = n0 + warp_n * 32 + ni * 8 + (lane & 3) * 2;
            if (n < N) {
                float bx = 0.f, by = 0.f;
                if (bias) { bx = bias[n]; by = bias[n + 1]; }
                if (m < M) {
                    float2 o = make_float2(acc[mi][ni][0] + bx, acc[mi][ni][1] + by);
                    *(float2*)(Cm + (size_t)m * ldc + n) = o;
                }
                if (m + 8 < M) {
                    float2 o = make_float2(acc[mi][ni][2] + bx, acc[mi][ni][3] + by);
                    *(float2*)(Cm + (size_t)(m + 8) * ldc + n) = o;
                }
            }
        }
    }
}

// ---------------- prologue kernels ----------------

__global__ void mean_kernel(const float* __restrict__ img) {
    int w = (blockIdx.x * blockDim.x + threadIdx.x) >> 5;
    int lane = threadIdx.x & 31;
    if (w >= BB * CC) return;
    const float* p = img + (size_t)w * HWD;
    float s = 0.f;
    for (int k = lane; k < HWD; k += 32) s += p[k];
    #pragma unroll
    for (int o = 16; o; o >>= 1) s += __shfl_xor_sync(0xFFFFFFFFu, s, o);
    if (!lane) g_fm[w] = s * (1.0f / HWD);
}

// featsT split: ftT[b*HW + k][c] = img[b][c][k]
__global__ void transpose_kernel(const float* __restrict__ img) {
    __shared__ float tile[32][33];
    int b = blockIdx.z;
    int k0 = blockIdx.x * 32, c0 = blockIdx.y * 32;
    int tx = threadIdx.x, ty = threadIdx.y;
    for (int i = ty; i < 32; i += 8) {
        int c = c0 + i, k = k0 + tx;
        tile[i][tx] = (c < CC && k < HWD) ? img[((size_t)b * CC + c) * HWD + k] : 0.f;
    }
    __syncthreads();
    for (int i = ty; i < 32; i += 8) {
        int k = k0 + i, c = c0 + tx;
        if (k < HWD && c < CC) {
            size_t idx = ((size_t)b * HWD + k) * CC + c;
            split2(tile[tx][i], &g_ftT_h[idx], &g_ftT_l[idx]);
        }
    }
}

__global__ void split_kernel(const float* __restrict__ src,
                             __nv_bfloat16* __restrict__ dh,
                             __nv_bfloat16* __restrict__ dl, int n) {
    int stride = gridDim.x * blockDim.x;
    for (int i = blockIdx.x * blockDim.x + threadIdx.x; i < n; i += stride)
        split2(src[i], &dh[i], &dl[i]);
}

// Wcat split from W_ih|W_hh, + bcat
__global__ void wcat_kernel(const float* __restrict__ W_ih, const float* __restrict__ b_ih,
                            const float* __restrict__ W_hh, const float* __restrict__ b_hh) {
    int stride = gridDim.x * blockDim.x;
    int t0 = blockIdx.x * blockDim.x + threadIdx.x;
    for (int i = t0; i < G4 * XD; i += stride) {
        int j = i / XD, c = i - j * XD;
        float v = (c < IHK) ? W_ih[(size_t)j * IHK + c]
                            : W_hh[(size_t)j * UU + (c - IHK)];
        split2(v, &g_Wcat_h[i], &g_Wcat_l[i]);
    }
    if (t0 < G4) g_bcat[t0] = b_ih[t0] + b_hh[t0];
}

__global__ void init_hc_kernel(const float* __restrict__ W_h0, const float* __restrict__ b_h0,
                               const float* __restrict__ W_c0, const float* __restrict__ b_c0) {
    int w = (blockIdx.x * blockDim.x + threadIdx.x) >> 5;
    int lane = threadIdx.x & 31;
    if (w >= BB * UU) return;
    int b = w / UU, u = w % UU;
    const float* fm = g_fm + b * CC;
    const float* wh = W_h0 + (size_t)u * CC;
    const float* wc = W_c0 + (size_t)u * CC;
    float sh = 0.f, sc = 0.f;
    for (int c = lane; c < CC; c += 32) {
        float f = fm[c];
        sh += f * wh[c];
        sc += f * wc[c];
    }
    #pragma unroll
    for (int o = 16; o; o >>= 1) {
        sh += __shfl_xor_sync(0xFFFFFFFFu, sh, o);
        sc += __shfl_xor_sync(0xFFFFFFFFu, sc, o);
    }
    if (!lane) {
        g_hid[w]  = sh + b_h0[u];
        g_cell[w] = sc + b_c0[u];
    }
}

__global__ void emb_kernel(const int* __restrict__ cap, const float* __restrict__ emb) {
    int w = (blockIdx.x * blockDim.x + threadIdx.x) >> 5;
    int lane = threadIdx.x & 31;
    if (w >= BB * TT) return;
    int idx = cap[w];
    const float* row = emb + (size_t)idx * EE;
    float v[8];
    float ss = 0.f;
    #pragma unroll
    for (int i = 0; i < 8; i++) { v[i] = row[lane + 32 * i]; ss += v[i] * v[i]; }
    #pragma unroll
    for (int o = 16; o; o >>= 1) ss += __shfl_xor_sync(0xFFFFFFFFu, ss, o);
    float norm = sqrtf(ss);
    float sc = fminf(1.0f, 5.0f / fmaxf(norm, 1e-12f));
    #pragma unroll
    for (int i = 0; i < 8; i++) g_capemb[(size_t)w * EE + lane + 32 * i] = v[i] * sc;
}

// ============================================================================
// Fused per-step: LSTM(t-1) update + attention(t) + packing. grid=BB, 256 thr.
// t==0: no LSTM (uses init hid). t==TT: LSTM only (final step), no attention.
// ============================================================================
__global__ void att_lstm(const float* __restrict__ img, float* __restrict__ attn_out, int t) {
    __shared__ float hid_s[UU];
    __shared__ float w_s[HWD];
    __shared__ float red[256];
    int b = blockIdx.x, tid = threadIdx.x, wid = tid >> 5, lane = tid & 31;

    if (t > 0) {
        // LSTM update for step t-1
        for (int u = tid; u < UU; u += 256) {
            float gi = g_bcat[u], gf = g_bcat[UU + u], gg = g_bcat[2 * UU + u], go = g_bcat[3 * UU + u];
            #pragma unroll
            for (int s = 0; s < KSPLIT; s++) {
                const float* p = g_gpart + ((size_t)s * BB + b) * G4;
                gi += p[u]; gf += p[UU + u]; gg += p[2 * UU + u]; go += p[3 * UU + u];
            }
            float si = 1.f / (1.f + expf(-gi));
            float sf = 1.f / (1.f + expf(-gf));
            float so = 1.f / (1.f + expf(-go));
            float c = sf * g_cell[b * UU + u] + si * tanhf(gg);
            float h = so * tanhf(c);
            g_cell[b * UU + u] = c;
            g_hid[b * UU + u]  = h;
            hid_s[u] = h;
            size_t oo = ((size_t)(b * TT + (t - 1))) * XD + u;
            split2(h, &g_outs_h[oo], &g_outs_l[oo]);
            if (t < TT) {
                size_t xo = (size_t)b * XD + IHK + u;
                split2(h, &g_x_h[xo], &g_x_l[xo]);
            }
        }
        if (t == TT) return;
    } else {
        for (int u = tid; u < UU; u += 256) {
            float h = g_hid[b * UU + u];
            hid_s[u] = h;
            size_t xo = (size_t)b * XD + IHK + u;
            split2(h, &g_x_h[xo], &g_x_l[xo]);
        }
    }
    __syncthreads();

    // scores: one warp per key row
    for (int k = wid; k < HWD; k += 8) {
        const float* kp = g_keys + ((size_t)b * HWD + k) * UU;
        float s = 0.f;
        for (int u = lane; u < UU; u += 32) s += hid_s[u] * kp[u];
        #pragma unroll
        for (int o = 16; o; o >>= 1) s += __shfl_xor_sync(0xFFFFFFFFu, s, o);
        if (!lane) w_s[k] = s * 0.044194173824159216f;
    }
    __syncthreads();

    // softmax over HW
    float v = (tid < HWD) ? w_s[tid] : -1e30f;
    red[tid] = v;
    __syncthreads();
    for (int s = 128; s; s >>= 1) { if (tid < s) red[tid] = fmaxf(red[tid], red[tid + s]); __syncthreads(); }
    float mx = red[0];
    __syncthreads();
    float e = (tid < HWD) ? expf(v - mx) : 0.f;
    red[tid] = e;
    __syncthreads();
    for (int s = 128; s; s >>= 1) { if (tid < s) red[tid] += red[tid + s]; __syncthreads(); }
    float inv = 1.0f / red[0];
    if (tid < HWD) {
        float wv = e * inv;
        w_s[tid] = wv;
        if (attn_out) attn_out[((size_t)b * TT + t) * HWD + tid] = wv;
    }
    __syncthreads();

    // attend: one warp per channel
    for (int c = wid; c < CC; c += 8) {
        const float* ip = img + ((size_t)b * CC + c) * HWD;
        float s = 0.f;
        for (int k = lane; k < HWD; k += 32) s += w_s[k] * ip[k];
        #pragma unroll
        for (int o = 16; o; o >>= 1) s += __shfl_xor_sync(0xFFFFFFFFu, s, o);
        if (!lane) {
            size_t xo = (size_t)b * XD + EE + c;
            split2(s, &g_x_h[xo], &g_x_l[xo]);
            size_t oo = ((size_t)(b * TT + t)) * XD + UU + c;
            split2(s, &g_outs_h[oo], &g_outs_l[oo]);
        }
    }

    // pack emb_t
    for (int r = tid; r < EE; r += 256) {
        float e2 = g_capemb[((size_t)(b * TT + t)) * EE + r];
        size_t xo = (size_t)b * XD + r;
        split2(e2, &g_x_h[xo], &g_x_l[xo]);
        size_t oo = ((size_t)(b * TT + t)) * XD + UU + CC + r;
        split2(e2, &g_outs_h[oo], &g_outs_l[oo]);
    }
}

// ---------------- host ----------------
template <typename T>
static T* symaddr(const void* sym) {
    void* p = nullptr;
    cudaGetSymbolAddress(&p, sym);
    return (T*)p;
}

extern "C" void kernel_launch(void* const* d_in, const int* in_sizes, int n_in,
                              void* d_out, int out_size) {
    const float* img   = (const float*)d_in[0];
    const int*   cap   = (const int*)d_in[1];
    const float* W_h0  = (const float*)d_in[2];
    const float* b_h0  = (const float*)d_in[3];
    const float* W_c0  = (const float*)d_in[4];
    const float* b_c0  = (const float*)d_in[5];
    const float* emb   = (const float*)d_in[6];
    const float* W_key = (const float*)d_in[7];
    const float* b_key = (const float*)d_in[8];
    const float* W_ih  = (const float*)d_in[9];
    const float* b_ih  = (const float*)d_in[10];
    const float* W_hh  = (const float*)d_in[11];
    const float* b_hh  = (const float*)d_in[12];
    const float* W_out = (const float*)d_in[13];
    const float* b_out = (const float*)d_in[14];
    float* out = (float*)d_out;

    __nv_bfloat16* p_ftT_h  = symaddr<__nv_bfloat16>(g_ftT_h);
    __nv_bfloat16* p_ftT_l  = symaddr<__nv_bfloat16>(g_ftT_l);
    __nv_bfloat16* p_Wkey_h = symaddr<__nv_bfloat16>(g_Wkey_h);
    __nv_bfloat16* p_Wkey_l = symaddr<__nv_bfloat16>(g_Wkey_l);
    __nv_bfloat16* p_Wcat_h = symaddr<__nv_bfloat16>(g_Wcat_h);
    __nv_bfloat16* p_Wcat_l = symaddr<__nv_bfloat16>(g_Wcat_l);
    __nv_bfloat16* p_Wout_h = symaddr<__nv_bfloat16>(g_Wout_h);
    __nv_bfloat16* p_Wout_l = symaddr<__nv_bfloat16>(g_Wout_l);
    __nv_bfloat16* p_x_h    = symaddr<__nv_bfloat16>(g_x_h);
    __nv_bfloat16* p_x_l    = symaddr<__nv_bfloat16>(g_x_l);
    __nv_bfloat16* p_outs_h = symaddr<__nv_bfloat16>(g_outs_h);
    __nv_bfloat16* p_outs_l = symaddr<__nv_bfloat16>(g_outs_l);
    float* p_keys  = symaddr<float>(g_keys);
    float* p_gpart = symaddr<float>(g_gpart);

    float* attn_out = (out_size >= LOGITS_SZ + ATTN_SZ) ? (out + LOGITS_SZ) : nullptr;

    // 1-3: prologue needed by keys GEMM
    transpose_kernel<<<dim3(7, 16, BB), dim3(32, 8)>>>(img);
    split_kernel<<<256, 256>>>(W_key, p_Wkey_h, p_Wkey_l, UU * CC);
    mean_kernel<<<(BB * CC / 8), 256>>>(img);

    // 4 (profiled slot): keys = featsT @ W_key^T + b_key : M=12544, N=512, K=512
    hgemm<<<dim3(UU / 128, (BB * HWD) / 128, 1), 256>>>(
        p_ftT_h, p_ftT_l, CC, p_Wkey_h, p_Wkey_l, CC, b_key, p_keys, UU,
        BB * HWD, UU, CC);

    emb_kernel<<<(BB * TT + 7) / 8, 256>>>(cap, emb);
    init_hc_kernel<<<(BB * UU / 8), 256>>>(W_h0, b_h0, W_c0, b_c0);
    wcat_kernel<<<1024, 256>>>(W_ih, b_ih, W_hh, b_hh);
    split_kernel<<<2048, 256>>>(W_out, p_Wout_h, p_Wout_l, VV * XD);

    for (int t = 0; t < TT; t++) {
        att_lstm<<<BB, 256>>>(img, attn_out, t);
        // gates partials = x @ Wcat^T (split-K) : M=64, N=2048, K=1280
        hgemm<<<dim3(G4 / 128, 1, KSPLIT), 256>>>(
            p_x_h, p_x_l, XD, p_Wcat_h, p_Wcat_l, XD, nullptr, p_gpart, G4,
            BB, G4, XD);
    }
    // final LSTM update (t=19 outputs into outs)
    att_lstm<<<BB, 256>>>(img, nullptr, TT);

    // logits = outs @ W_out^T + b_out : M=1280, N=10000, K=1280
    hgemm<<<dim3((VV + 127) / 128, (BB * TT) / 128, 1), 256>>>(
        p_outs_h, p_outs_l, XD, p_Wout_h, p_Wout_l, XD, b_out, out, VV,
        BB * TT, VV, XD);
}